// round 15
// baseline (speedup 1.0000x reference)
#include <cuda_runtime.h>
#include <cstdint>
#include <cstddef>

// SelfAttention: out = softmax(Q K^T / 8 + bias, mask) @ V
// B=4, H=16, L=2048, D=64, fp32.  tf32 mma.sync (legacy HMMA — family-portable,
// works on base sm_103 PTX target; tcgen05 rejected by this toolchain).
//
// Per CTA (256 thr, 8 warps): 128 q-rows (16/warp), loop 16 k-tiles of 128.
//  GEMM1: S(16x128/warp) = Q·K^T via m16n8k8 tf32; Q persistent in A-frags.
//  Max-free log2-domain softmax in registers; P overwrites S fragments.
//  GEMM2: O += P·V; A-frags built from C-frags via quad shuffles.
// k-columns permuted (perm-invariant under softmax sum) so each thread's
// C-fragment columns are CONTIGUOUS logical bias columns -> coalesced bias LDG.

#define B_  4
#define H_  16
#define L_  2048
#define D_  64
#define BQ  128
#define BN  128
#define NKT (L_ / BN)   // 16
#define NQT (L_ / BQ)   // 16

#define KS_STR 68   // floats; bank-perm (4*g + j) unique -> conflict-free B-frag LDS
#define VS_STR 72   // floats; bank-perm (8*j + g) unique -> conflict-free B-frag LDS

#define OFF_K 0
#define OFF_V (128 * KS_STR * 4)              // 34816
#define OFF_M (OFF_V + 128 * VS_STR * 4)      // 71680
#define SMEM_BYTES (OFF_M + 512)              // 72192

__device__ __forceinline__ float ex2f(float x) {
    float y; asm("ex2.approx.ftz.f32 %0, %1;" : "=f"(y) : "f"(x)); return y;
}
__device__ __forceinline__ float tf32r(float x) {   // round-to-nearest tf32
    float y; asm("cvt.rna.tf32.f32 %0, %1;" : "=f"(y) : "f"(x)); return y;
}
__device__ __forceinline__ void mma8(float* c, const uint32_t* a,
                                     uint32_t b0, uint32_t b1) {
    asm volatile(
        "mma.sync.aligned.m16n8k8.row.col.f32.tf32.tf32.f32 "
        "{%0,%1,%2,%3}, {%4,%5,%6,%7}, {%8,%9}, {%0,%1,%2,%3};"
        : "+f"(c[0]), "+f"(c[1]), "+f"(c[2]), "+f"(c[3])
        : "r"(a[0]), "r"(a[1]), "r"(a[2]), "r"(a[3]), "r"(b0), "r"(b1));
}

extern __shared__ char smem_raw[];

__global__ __launch_bounds__(256, 1)
void SelfAttention_53369263620701_kernel(
    const float* __restrict__ Q, const float* __restrict__ K,
    const float* __restrict__ V, const int* __restrict__ AM,
    const float* __restrict__ BIAS, float* __restrict__ OUT)
{
    float* Ks  = (float*)(smem_raw + OFF_K);   // [p][d] physical order, stride 68
    float* Vs  = (float*)(smem_raw + OFF_V);   // [p][d] physical order, stride 72
    float* Msl = (float*)(smem_raw + OFF_M);   // [l] logical order mask-additive

    const int tid  = threadIdx.x;
    const int wid  = tid >> 5;
    const int lane = tid & 31;
    const int g    = lane >> 2;   // group id (row within m16)
    const int j    = lane & 3;    // thread-in-group (col quad pos)

    const int h  = blockIdx.x;    // h fastest: 16 heads share bias rows in L2
    const int qt = blockIdx.y;
    const int b  = blockIdx.z;
    const int q0 = qt * BQ;
    const int qw = q0 + wid * 16; // this warp's first q-row

    const size_t bh = (size_t)b * H_ + h;
    const float* Qp = Q + bh * (size_t)(L_ * D_);
    const float* Kp = K + bh * (size_t)(L_ * D_);
    const float* Vp = V + bh * (size_t)(L_ * D_);
    const float* Bp = BIAS + (size_t)b * L_ * L_;
    const int*   Mp = AM + b * L_;

    // ---- Q A-fragments, persistent (tf32-rounded): row g / g+8, col 8s+j / +4 ----
    uint32_t Qa[8][4];
    {
        const float* r0 = Qp + (size_t)(qw + g) * D_ + j;
        const float* r1 = r0 + 8 * D_;
        #pragma unroll
        for (int s = 0; s < 8; ++s) {
            Qa[s][0] = __float_as_uint(tf32r(r0[8 * s]));
            Qa[s][1] = __float_as_uint(tf32r(r1[8 * s]));
            Qa[s][2] = __float_as_uint(tf32r(r0[8 * s + 4]));
            Qa[s][3] = __float_as_uint(tf32r(r1[8 * s + 4]));
        }
    }

    float Oc[8][4];
    #pragma unroll
    for (int nt = 0; nt < 8; ++nt)
        #pragma unroll
        for (int e = 0; e < 4; ++e) Oc[nt][e] = 0.f;
    float l0 = 0.f, l1 = 0.f;   // per-thread partial row sums (quad-reduced at end)

    const float C1 = 0.125f * 1.4426950408889634f;  // (1/sqrt(D)) * log2(e)
    const float C2 = 1.4426950408889634f;           // log2(e)

    // bias pointers: logical cols [32j, 32j+32) are exactly this thread's C cols
    const float* br0 = Bp + (size_t)(qw + g) * L_ + 32 * j;
    const float* br1 = br0 + (size_t)8 * L_;

    for (int kt = 0; kt < NKT; ++kt) {
        const int k0 = kt * BN;
        __syncthreads();  // prev iteration's GEMM2 done with Ks/Vs

        // ---- stage K,V tiles in PHYSICAL column order: row p <- logical pi(p) ----
        #pragma unroll
        for (int i = 0; i < 8; ++i) {
            int idx = tid + (i << 8);
            int p  = idx >> 4;
            int c4 = (idx & 15) << 2;
            int l  = ((p >> 1) & 3) * 32 + ((p >> 3) << 1) + (p & 1);  // pi(p)
            float4 kv = *(const float4*)(Kp + (size_t)(k0 + l) * D_ + c4);
            kv.x = tf32r(kv.x); kv.y = tf32r(kv.y); kv.z = tf32r(kv.z); kv.w = tf32r(kv.w);
            *(float4*)(Ks + p * KS_STR + c4) = kv;
            float4 vv = *(const float4*)(Vp + (size_t)(k0 + l) * D_ + c4);
            vv.x = tf32r(vv.x); vv.y = tf32r(vv.y); vv.z = tf32r(vv.z); vv.w = tf32r(vv.w);
            *(float4*)(Vs + p * VS_STR + c4) = vv;
        }
        if (tid < BN) Msl[tid] = Mp[k0 + tid] ? 0.f : -1.0e30f;  // logical order
        __syncthreads();

        // ---- GEMM1: S = Q @ K^T (physical cols) ----
        float Sc[16][4];
        #pragma unroll
        for (int nt = 0; nt < 16; ++nt)
            #pragma unroll
            for (int e = 0; e < 4; ++e) Sc[nt][e] = 0.f;

        #pragma unroll
        for (int nt = 0; nt < 16; ++nt) {
            const float* kb = Ks + (8 * nt + g) * KS_STR + j;
            #pragma unroll
            for (int s = 0; s < 8; ++s) {
                uint32_t b0 = __float_as_uint(kb[8 * s]);
                uint32_t b1 = __float_as_uint(kb[8 * s + 4]);
                mma8(Sc[nt], Qa[s], b0, b1);
            }
        }

        // ---- softmax: P = tf32(exp2(S*C1 + bias*C2 + madd)); contiguous bias loads ----
        #pragma unroll
        for (int hf = 0; hf < 2; ++hf) {
            float4 bb0[4], bb1[4], mm[4];
            #pragma unroll
            for (int f = 0; f < 4; ++f) {
                bb0[f] = *(const float4*)(br0 + k0 + hf * 16 + 4 * f);
                bb1[f] = *(const float4*)(br1 + k0 + hf * 16 + 4 * f);
                mm[f]  = *(const float4*)(Msl + 32 * j + hf * 16 + 4 * f);
            }
            #pragma unroll
            for (int t = 0; t < 8; ++t) {
                const int nt = hf * 8 + t;
                const int f = t >> 1, c = (t & 1) << 1;
                const float* B0 = (const float*)&bb0[f];
                const float* B1 = (const float*)&bb1[f];
                const float* M0 = (const float*)&mm[f];
                float p0 = tf32r(ex2f(fmaf(Sc[nt][0], C1, fmaf(B0[c],     C2, M0[c]))));
                float p1 = tf32r(ex2f(fmaf(Sc[nt][1], C1, fmaf(B0[c + 1], C2, M0[c + 1]))));
                float p2 = tf32r(ex2f(fmaf(Sc[nt][2], C1, fmaf(B1[c],     C2, M0[c]))));
                float p3 = tf32r(ex2f(fmaf(Sc[nt][3], C1, fmaf(B1[c + 1], C2, M0[c + 1]))));
                l0 += p0 + p1;
                l1 += p2 + p3;
                Sc[nt][0] = p0; Sc[nt][1] = p1; Sc[nt][2] = p2; Sc[nt][3] = p3;
            }
        }

        // ---- GEMM2: O += P @ V (A-frags from C-frags via quad shuffles) ----
        const int srcA = (lane & ~3) | (j >> 1);
        const int srcB = srcA + 2;
        const bool hi  = (j & 1) != 0;
        #pragma unroll
        for (int s = 0; s < 16; ++s) {
            float x0 = __shfl_sync(0xffffffffu, Sc[s][0], srcA);
            float x1 = __shfl_sync(0xffffffffu, Sc[s][1], srcA);
            float x2 = __shfl_sync(0xffffffffu, Sc[s][2], srcA);
            float x3 = __shfl_sync(0xffffffffu, Sc[s][3], srcA);
            float y0 = __shfl_sync(0xffffffffu, Sc[s][0], srcB);
            float y1 = __shfl_sync(0xffffffffu, Sc[s][1], srcB);
            float y2 = __shfl_sync(0xffffffffu, Sc[s][2], srcB);
            float y3 = __shfl_sync(0xffffffffu, Sc[s][3], srcB);
            uint32_t pa[4];
            pa[0] = __float_as_uint(hi ? x1 : x0);  // (g,   8s+j)
            pa[1] = __float_as_uint(hi ? x3 : x2);  // (g+8, 8s+j)
            pa[2] = __float_as_uint(hi ? y1 : y0);  // (g,   8s+j+4)
            pa[3] = __float_as_uint(hi ? y3 : y2);  // (g+8, 8s+j+4)
            const float* vb = Vs + (8 * s + j) * VS_STR + g;
            #pragma unroll
            for (int nt = 0; nt < 8; ++nt) {
                uint32_t b0 = __float_as_uint(vb[8 * nt]);
                uint32_t b1 = __float_as_uint(vb[8 * nt + 4 * VS_STR]);
                mma8(Oc[nt], pa, b0, b1);
            }
        }
    }

    // ---- epilogue: quad-reduce row sums, normalize, store ----
    l0 += __shfl_xor_sync(0xffffffffu, l0, 1);
    l0 += __shfl_xor_sync(0xffffffffu, l0, 2);
    l1 += __shfl_xor_sync(0xffffffffu, l1, 1);
    l1 += __shfl_xor_sync(0xffffffffu, l1, 2);
    const float i0 = 1.0f / l0;
    const float i1 = 1.0f / l1;

    float* o0 = OUT + bh * (size_t)(L_ * D_) + (size_t)(qw + g) * D_ + 2 * j;
    float* o1 = o0 + 8 * D_;
    #pragma unroll
    for (int nt = 0; nt < 8; ++nt) {
        *(float2*)(o0 + 8 * nt) = make_float2(Oc[nt][0] * i0, Oc[nt][1] * i0);
        *(float2*)(o1 + 8 * nt) = make_float2(Oc[nt][2] * i1, Oc[nt][3] * i1);
    }
}

extern "C" void kernel_launch(void* const* d_in, const int* in_sizes, int n_in,
                              void* d_out, int out_size)
{
    const float* Q    = (const float*)d_in[0];
    const float* K    = (const float*)d_in[1];
    const float* V    = (const float*)d_in[2];
    const int*   AM   = (const int*)d_in[3];
    const float* BIAS = (const float*)d_in[4];
    float*       OUT  = (float*)d_out;

    cudaFuncSetAttribute(SelfAttention_53369263620701_kernel,
                         cudaFuncAttributeMaxDynamicSharedMemorySize, SMEM_BYTES);

    dim3 grid(H_, NQT, B_);   // h fastest: co-scheduled heads share bias rows in L2
    dim3 block(256);
    SelfAttention_53369263620701_kernel<<<grid, block, SMEM_BYTES>>>(
        Q, K, V, AM, BIAS, OUT);
}

// round 16
// speedup vs baseline: 1.0832x; 1.0832x over previous
#include <cuda_runtime.h>
#include <cstdint>
#include <cstddef>

// SelfAttention: out = softmax(Q K^T / 8 + bias, mask) @ V
// B=4, H=16, L=2048, D=64, fp32. tf32 mma.sync flash-attention, max-free softmax.
//
// R15: 8 warps = 4 q-groups x 2 k-halves. Each warp: 32 q-rows x 64 k-cols.
// B-fragments (K,V) shared across the two 16-row m-tiles -> smem read traffic
// halved vs R14 (the 82% L1 bottleneck). S fragments are transient: per 8-col
// n-tile we do GEMM1 -> softmax -> shuffle -> GEMM2 immediately (max-free),
// keeping registers ~230. O and row sums are per-k-half partials merged in a
// one-time smem epilogue.

#define B_  4
#define H_  16
#define L_  2048
#define D_  64
#define BQ  128
#define BN  128
#define NKT (L_ / BN)   // 16
#define NQT (L_ / BQ)   // 16

#define KS_STR 68   // banks 4g+j unique -> conflict-free GEMM1 B loads
#define VS_STR 72   // banks 8j+g unique -> conflict-free GEMM2 B loads

#define OFF_K 0
#define OFF_V (128 * KS_STR * 4)              // 34816
#define OFF_M (OFF_V + 128 * VS_STR * 4)      // 71680
#define SMEM_BYTES (OFF_M + 512)              // 72192

// epilogue scratch (reuses Ks region after final sync)
#define OS_STR 66
#define OFF_LS (128 * OS_STR * 4)             // 33792 (< OFF_V)

__device__ __forceinline__ float ex2f(float x) {
    float y; asm("ex2.approx.ftz.f32 %0, %1;" : "=f"(y) : "f"(x)); return y;
}
__device__ __forceinline__ float tf32r(float x) {   // round-to-nearest tf32
    float y; asm("cvt.rna.tf32.f32 %0, %1;" : "=f"(y) : "f"(x)); return y;
}
__device__ __forceinline__ void mma8(float* c, const uint32_t* a,
                                     uint32_t b0, uint32_t b1) {
    asm volatile(
        "mma.sync.aligned.m16n8k8.row.col.f32.tf32.tf32.f32 "
        "{%0,%1,%2,%3}, {%4,%5,%6,%7}, {%8,%9}, {%0,%1,%2,%3};"
        : "+f"(c[0]), "+f"(c[1]), "+f"(c[2]), "+f"(c[3])
        : "r"(a[0]), "r"(a[1]), "r"(a[2]), "r"(a[3]), "r"(b0), "r"(b1));
}

extern __shared__ char smem_raw[];

__global__ __launch_bounds__(256, 1)
void SelfAttention_53369263620701_kernel(
    const float* __restrict__ Q, const float* __restrict__ K,
    const float* __restrict__ V, const int* __restrict__ AM,
    const float* __restrict__ BIAS, float* __restrict__ OUT)
{
    float* Ks  = (float*)(smem_raw + OFF_K);   // [p][d] physical rows, stride 68
    float* Vs  = (float*)(smem_raw + OFF_V);   // [p][d] physical rows, stride 72
    float* Msl = (float*)(smem_raw + OFF_M);   // [l] logical-order mask additive

    const int tid  = threadIdx.x;
    const int wid  = tid >> 5;
    const int lane = tid & 31;
    const int g    = lane >> 2;
    const int j    = lane & 3;
    const int wq   = wid & 3;     // q-group (32 rows each)
    const int kh   = wid >> 2;    // k-half (64 phys cols each)

    const int h  = blockIdx.x;    // h fastest: 16 heads share bias rows in L2
    const int qt = blockIdx.y;
    const int b  = blockIdx.z;
    const int q0 = qt * BQ;
    const int qw = q0 + wq * 32;  // this warp's first q-row (global)

    const size_t bh = (size_t)b * H_ + h;
    const float* Qp = Q + bh * (size_t)(L_ * D_);
    const float* Kp = K + bh * (size_t)(L_ * D_);
    const float* Vp = V + bh * (size_t)(L_ * D_);
    const float* Bp = BIAS + (size_t)b * L_ * L_;
    const int*   Mp = AM + b * L_;

    // ---- Q A-fragments, persistent (tf32-rounded). 2 m-tiles of 16 rows. ----
    uint32_t Qa[2][8][4];
    #pragma unroll
    for (int mt = 0; mt < 2; ++mt) {
        const float* r0 = Qp + (size_t)(qw + 16 * mt + g) * D_ + j;
        const float* r1 = r0 + 8 * D_;
        #pragma unroll
        for (int s = 0; s < 8; ++s) {
            Qa[mt][s][0] = __float_as_uint(tf32r(r0[8 * s]));
            Qa[mt][s][1] = __float_as_uint(tf32r(r1[8 * s]));
            Qa[mt][s][2] = __float_as_uint(tf32r(r0[8 * s + 4]));
            Qa[mt][s][3] = __float_as_uint(tf32r(r1[8 * s + 4]));
        }
    }

    float Oc[2][8][4];
    #pragma unroll
    for (int mt = 0; mt < 2; ++mt)
        #pragma unroll
        for (int nd = 0; nd < 8; ++nd)
            #pragma unroll
            for (int e = 0; e < 4; ++e) Oc[mt][nd][e] = 0.f;
    float lacc[4] = {0.f, 0.f, 0.f, 0.f};   // [2mt + rowhalf], partial over j & kh

    const float C1 = 0.125f * 1.4426950408889634f;  // (1/sqrt(D)) * log2(e)
    const float C2 = 1.4426950408889634f;           // log2(e)

    // bias row pointers: rows qw+{g, g+8, g+16, g+24}, col window 64kh+16j
    const float* bp0 = Bp + (size_t)(qw + g) * L_ + 64 * kh + 16 * j;
    const float* bp1 = bp0 + (size_t)(8)  * L_;
    const float* bp2 = bp0 + (size_t)(16) * L_;
    const float* bp3 = bp0 + (size_t)(24) * L_;

    const int srcA = (lane & ~3) | (j >> 1);
    const int srcB = srcA + 2;
    const bool hi  = (j & 1) != 0;

    for (int kt = 0; kt < NKT; ++kt) {
        const int k0 = kt * BN;
        __syncthreads();  // previous iteration done with Ks/Vs/Msl

        // ---- stage K,V: physical row p <- logical pi(p) ----
        // pi: kh=p>>6, nt=(p>>3)&7, j'=(p>>1)&3, u=p&1 -> l = 64kh + 16j' + 2nt + u
        #pragma unroll
        for (int i = 0; i < 8; ++i) {
            int idx = tid + (i << 8);
            int p  = idx >> 4;
            int c4 = (idx & 15) << 2;
            int l  = ((p >> 6) << 6) + (((p >> 1) & 3) << 4)
                   + (((p >> 3) & 7) << 1) + (p & 1);
            float4 kv = *(const float4*)(Kp + (size_t)(k0 + l) * D_ + c4);
            kv.x = tf32r(kv.x); kv.y = tf32r(kv.y); kv.z = tf32r(kv.z); kv.w = tf32r(kv.w);
            *(float4*)(Ks + p * KS_STR + c4) = kv;
            float4 vv = *(const float4*)(Vp + (size_t)(k0 + l) * D_ + c4);
            vv.x = tf32r(vv.x); vv.y = tf32r(vv.y); vv.z = tf32r(vv.z); vv.w = tf32r(vv.w);
            *(float4*)(Vs + p * VS_STR + c4) = vv;
        }
        if (tid < BN) Msl[tid] = Mp[k0 + tid] ? 0.f : -1.0e30f;  // logical order
        __syncthreads();

        // ---- fused per-n-tile pipeline over this warp's 64 phys k-cols ----
        #pragma unroll
        for (int nt = 0; nt < 8; ++nt) {
            // GEMM1: Sf = Q . K^T for 32 rows x 8 phys cols (B shared across mt)
            float Sf0[4] = {0.f, 0.f, 0.f, 0.f};
            float Sf1[4] = {0.f, 0.f, 0.f, 0.f};
            const float* kb = Ks + (64 * kh + 8 * nt + g) * KS_STR + j;
            #pragma unroll
            for (int s = 0; s < 8; ++s) {
                uint32_t b0 = __float_as_uint(kb[8 * s]);
                uint32_t b1 = __float_as_uint(kb[8 * s + 4]);
                mma8(Sf0, Qa[0][s], b0, b1);
                mma8(Sf1, Qa[1][s], b0, b1);
            }

            // softmax (max-free, log2 domain); P overwrites Sf
            float2 mm = *(const float2*)(Msl + 64 * kh + 16 * j + 2 * nt);
            {
                float2 b00 = *(const float2*)(bp0 + k0 + 2 * nt);
                float2 b01 = *(const float2*)(bp1 + k0 + 2 * nt);
                float p0 = tf32r(ex2f(fmaf(Sf0[0], C1, fmaf(b00.x, C2, mm.x))));
                float p1 = tf32r(ex2f(fmaf(Sf0[1], C1, fmaf(b00.y, C2, mm.y))));
                float p2 = tf32r(ex2f(fmaf(Sf0[2], C1, fmaf(b01.x, C2, mm.x))));
                float p3 = tf32r(ex2f(fmaf(Sf0[3], C1, fmaf(b01.y, C2, mm.y))));
                lacc[0] += p0 + p1; lacc[1] += p2 + p3;
                Sf0[0] = p0; Sf0[1] = p1; Sf0[2] = p2; Sf0[3] = p3;
            }
            {
                float2 b10 = *(const float2*)(bp2 + k0 + 2 * nt);
                float2 b11 = *(const float2*)(bp3 + k0 + 2 * nt);
                float p0 = tf32r(ex2f(fmaf(Sf1[0], C1, fmaf(b10.x, C2, mm.x))));
                float p1 = tf32r(ex2f(fmaf(Sf1[1], C1, fmaf(b10.y, C2, mm.y))));
                float p2 = tf32r(ex2f(fmaf(Sf1[2], C1, fmaf(b11.x, C2, mm.x))));
                float p3 = tf32r(ex2f(fmaf(Sf1[3], C1, fmaf(b11.y, C2, mm.y))));
                lacc[2] += p0 + p1; lacc[3] += p2 + p3;
                Sf1[0] = p0; Sf1[1] = p1; Sf1[2] = p2; Sf1[3] = p3;
            }

            // C-frag -> A-frag via quad shuffles (both m-tiles)
            uint32_t paA[4], paB[4];
            {
                float x0 = __shfl_sync(0xffffffffu, Sf0[0], srcA);
                float x1 = __shfl_sync(0xffffffffu, Sf0[1], srcA);
                float x2 = __shfl_sync(0xffffffffu, Sf0[2], srcA);
                float x3 = __shfl_sync(0xffffffffu, Sf0[3], srcA);
                float y0 = __shfl_sync(0xffffffffu, Sf0[0], srcB);
                float y1 = __shfl_sync(0xffffffffu, Sf0[1], srcB);
                float y2 = __shfl_sync(0xffffffffu, Sf0[2], srcB);
                float y3 = __shfl_sync(0xffffffffu, Sf0[3], srcB);
                paA[0] = __float_as_uint(hi ? x1 : x0);
                paA[1] = __float_as_uint(hi ? x3 : x2);
                paA[2] = __float_as_uint(hi ? y1 : y0);
                paA[3] = __float_as_uint(hi ? y3 : y2);
            }
            {
                float x0 = __shfl_sync(0xffffffffu, Sf1[0], srcA);
                float x1 = __shfl_sync(0xffffffffu, Sf1[1], srcA);
                float x2 = __shfl_sync(0xffffffffu, Sf1[2], srcA);
                float x3 = __shfl_sync(0xffffffffu, Sf1[3], srcA);
                float y0 = __shfl_sync(0xffffffffu, Sf1[0], srcB);
                float y1 = __shfl_sync(0xffffffffu, Sf1[1], srcB);
                float y2 = __shfl_sync(0xffffffffu, Sf1[2], srcB);
                float y3 = __shfl_sync(0xffffffffu, Sf1[3], srcB);
                paB[0] = __float_as_uint(hi ? x1 : x0);
                paB[1] = __float_as_uint(hi ? x3 : x2);
                paB[2] = __float_as_uint(hi ? y1 : y0);
                paB[3] = __float_as_uint(hi ? y3 : y2);
            }

            // GEMM2: O += P . V for this 8-col k-chunk (B shared across mt)
            const float* vb = Vs + (64 * kh + 8 * nt + j) * VS_STR + g;
            #pragma unroll
            for (int nd = 0; nd < 8; ++nd) {
                uint32_t b0 = __float_as_uint(vb[8 * nd]);
                uint32_t b1 = __float_as_uint(vb[8 * nd + 4 * VS_STR]);
                mma8(Oc[0][nd], paA, b0, b1);
                mma8(Oc[1][nd], paB, b0, b1);
            }
        }
    }

    // ---- epilogue: merge the two k-halves, normalize, store ----
    __syncthreads();
    #pragma unroll
    for (int e = 0; e < 4; ++e) {
        lacc[e] += __shfl_xor_sync(0xffffffffu, lacc[e], 1);
        lacc[e] += __shfl_xor_sync(0xffffffffu, lacc[e], 2);
    }
    float* Os = (float*)smem_raw;                 // [128][64] stride 66
    float* Ls = (float*)(smem_raw + OFF_LS);      // [128]

    if (kh == 1) {
        #pragma unroll
        for (int mt = 0; mt < 2; ++mt) {
            const int r0 = wq * 32 + 16 * mt + g;
            const int r1 = r0 + 8;
            #pragma unroll
            for (int nd = 0; nd < 8; ++nd) {
                *(float2*)(Os + r0 * OS_STR + 8 * nd + 2 * j) =
                    make_float2(Oc[mt][nd][0], Oc[mt][nd][1]);
                *(float2*)(Os + r1 * OS_STR + 8 * nd + 2 * j) =
                    make_float2(Oc[mt][nd][2], Oc[mt][nd][3]);
            }
            if (j == 0) { Ls[r0] = lacc[2 * mt]; Ls[r1] = lacc[2 * mt + 1]; }
        }
    }
    __syncthreads();
    if (kh == 0) {
        #pragma unroll
        for (int mt = 0; mt < 2; ++mt) {
            const int r0 = wq * 32 + 16 * mt + g;
            const int r1 = r0 + 8;
            const float i0 = 1.0f / (lacc[2 * mt]     + Ls[r0]);
            const float i1 = 1.0f / (lacc[2 * mt + 1] + Ls[r1]);
            float* o0 = OUT + bh * (size_t)(L_ * D_) + (size_t)(q0 + r0) * D_ + 2 * j;
            float* o1 = OUT + bh * (size_t)(L_ * D_) + (size_t)(q0 + r1) * D_ + 2 * j;
            #pragma unroll
            for (int nd = 0; nd < 8; ++nd) {
                float2 a = *(const float2*)(Os + r0 * OS_STR + 8 * nd + 2 * j);
                float2 c = *(const float2*)(Os + r1 * OS_STR + 8 * nd + 2 * j);
                *(float2*)(o0 + 8 * nd) =
                    make_float2((Oc[mt][nd][0] + a.x) * i0, (Oc[mt][nd][1] + a.y) * i0);
                *(float2*)(o1 + 8 * nd) =
                    make_float2((Oc[mt][nd][2] + c.x) * i1, (Oc[mt][nd][3] + c.y) * i1);
            }
        }
    }
}

extern "C" void kernel_launch(void* const* d_in, const int* in_sizes, int n_in,
                              void* d_out, int out_size)
{
    const float* Q    = (const float*)d_in[0];
    const float* K    = (const float*)d_in[1];
    const float* V    = (const float*)d_in[2];
    const int*   AM   = (const int*)d_in[3];
    const float* BIAS = (const float*)d_in[4];
    float*       OUT  = (float*)d_out;

    cudaFuncSetAttribute(SelfAttention_53369263620701_kernel,
                         cudaFuncAttributeMaxDynamicSharedMemorySize, SMEM_BYTES);

    dim3 grid(H_, NQT, B_);   // h fastest: co-scheduled heads share bias rows in L2
    dim3 block(256);
    SelfAttention_53369263620701_kernel<<<grid, block, SMEM_BYTES>>>(
        Q, K, V, AM, BIAS, OUT);
}

// round 17
// speedup vs baseline: 1.0859x; 1.0025x over previous
#include <cuda_runtime.h>
#include <cstdint>
#include <cstddef>

// SelfAttention: out = softmax(Q K^T / 8 + bias, mask) @ V
// B=4, H=16, L=2048, D=64, fp32. tf32 mma.sync flash-attention, max-free softmax.
//
// R15: 8 warps = 4 q-groups x 2 k-halves. Each warp: 32 q-rows x 64 k-cols.
// B-fragments (K,V) shared across the two 16-row m-tiles -> smem read traffic
// halved vs R14 (the 82% L1 bottleneck). S fragments are transient: per 8-col
// n-tile we do GEMM1 -> softmax -> shuffle -> GEMM2 immediately (max-free),
// keeping registers ~230. O and row sums are per-k-half partials merged in a
// one-time smem epilogue.

#define B_  4
#define H_  16
#define L_  2048
#define D_  64
#define BQ  128
#define BN  128
#define NKT (L_ / BN)   // 16
#define NQT (L_ / BQ)   // 16

#define KS_STR 68   // banks 4g+j unique -> conflict-free GEMM1 B loads
#define VS_STR 72   // banks 8j+g unique -> conflict-free GEMM2 B loads

#define OFF_K 0
#define OFF_V (128 * KS_STR * 4)              // 34816
#define OFF_M (OFF_V + 128 * VS_STR * 4)      // 71680
#define SMEM_BYTES (OFF_M + 512)              // 72192

// epilogue scratch (reuses Ks region after final sync)
#define OS_STR 66
#define OFF_LS (128 * OS_STR * 4)             // 33792 (< OFF_V)

__device__ __forceinline__ float ex2f(float x) {
    float y; asm("ex2.approx.ftz.f32 %0, %1;" : "=f"(y) : "f"(x)); return y;
}
__device__ __forceinline__ float tf32r(float x) {   // round-to-nearest tf32
    float y; asm("cvt.rna.tf32.f32 %0, %1;" : "=f"(y) : "f"(x)); return y;
}
__device__ __forceinline__ void mma8(float* c, const uint32_t* a,
                                     uint32_t b0, uint32_t b1) {
    asm volatile(
        "mma.sync.aligned.m16n8k8.row.col.f32.tf32.tf32.f32 "
        "{%0,%1,%2,%3}, {%4,%5,%6,%7}, {%8,%9}, {%0,%1,%2,%3};"
        : "+f"(c[0]), "+f"(c[1]), "+f"(c[2]), "+f"(c[3])
        : "r"(a[0]), "r"(a[1]), "r"(a[2]), "r"(a[3]), "r"(b0), "r"(b1));
}

extern __shared__ char smem_raw[];

__global__ __launch_bounds__(256, 1)
void SelfAttention_53369263620701_kernel(
    const float* __restrict__ Q, const float* __restrict__ K,
    const float* __restrict__ V, const int* __restrict__ AM,
    const float* __restrict__ BIAS, float* __restrict__ OUT)
{
    float* Ks  = (float*)(smem_raw + OFF_K);   // [p][d] physical rows, stride 68
    float* Vs  = (float*)(smem_raw + OFF_V);   // [p][d] physical rows, stride 72
    float* Msl = (float*)(smem_raw + OFF_M);   // [l] logical-order mask additive

    const int tid  = threadIdx.x;
    const int wid  = tid >> 5;
    const int lane = tid & 31;
    const int g    = lane >> 2;
    const int j    = lane & 3;
    const int wq   = wid & 3;     // q-group (32 rows each)
    const int kh   = wid >> 2;    // k-half (64 phys cols each)

    const int h  = blockIdx.x;    // h fastest: 16 heads share bias rows in L2
    const int qt = blockIdx.y;
    const int b  = blockIdx.z;
    const int q0 = qt * BQ;
    const int qw = q0 + wq * 32;  // this warp's first q-row (global)

    const size_t bh = (size_t)b * H_ + h;
    const float* Qp = Q + bh * (size_t)(L_ * D_);
    const float* Kp = K + bh * (size_t)(L_ * D_);
    const float* Vp = V + bh * (size_t)(L_ * D_);
    const float* Bp = BIAS + (size_t)b * L_ * L_;
    const int*   Mp = AM + b * L_;

    // ---- Q A-fragments, persistent (tf32-rounded). 2 m-tiles of 16 rows. ----
    uint32_t Qa[2][8][4];
    #pragma unroll
    for (int mt = 0; mt < 2; ++mt) {
        const float* r0 = Qp + (size_t)(qw + 16 * mt + g) * D_ + j;
        const float* r1 = r0 + 8 * D_;
        #pragma unroll
        for (int s = 0; s < 8; ++s) {
            Qa[mt][s][0] = __float_as_uint(tf32r(r0[8 * s]));
            Qa[mt][s][1] = __float_as_uint(tf32r(r1[8 * s]));
            Qa[mt][s][2] = __float_as_uint(tf32r(r0[8 * s + 4]));
            Qa[mt][s][3] = __float_as_uint(tf32r(r1[8 * s + 4]));
        }
    }

    float Oc[2][8][4];
    #pragma unroll
    for (int mt = 0; mt < 2; ++mt)
        #pragma unroll
        for (int nd = 0; nd < 8; ++nd)
            #pragma unroll
            for (int e = 0; e < 4; ++e) Oc[mt][nd][e] = 0.f;
    float lacc[4] = {0.f, 0.f, 0.f, 0.f};   // [2mt + rowhalf], partial over j & kh

    const float C1 = 0.125f * 1.4426950408889634f;  // (1/sqrt(D)) * log2(e)
    const float C2 = 1.4426950408889634f;           // log2(e)

    // bias row pointers: rows qw+{g, g+8, g+16, g+24}, col window 64kh+16j
    const float* bp0 = Bp + (size_t)(qw + g) * L_ + 64 * kh + 16 * j;
    const float* bp1 = bp0 + (size_t)(8)  * L_;
    const float* bp2 = bp0 + (size_t)(16) * L_;
    const float* bp3 = bp0 + (size_t)(24) * L_;

    const int srcA = (lane & ~3) | (j >> 1);
    const int srcB = srcA + 2;
    const bool hi  = (j & 1) != 0;

    for (int kt = 0; kt < NKT; ++kt) {
        const int k0 = kt * BN;
        __syncthreads();  // previous iteration done with Ks/Vs/Msl

        // ---- stage K,V: physical row p <- logical pi(p) ----
        // pi: kh=p>>6, nt=(p>>3)&7, j'=(p>>1)&3, u=p&1 -> l = 64kh + 16j' + 2nt + u
        #pragma unroll
        for (int i = 0; i < 8; ++i) {
            int idx = tid + (i << 8);
            int p  = idx >> 4;
            int c4 = (idx & 15) << 2;
            int l  = ((p >> 6) << 6) + (((p >> 1) & 3) << 4)
                   + (((p >> 3) & 7) << 1) + (p & 1);
            float4 kv = *(const float4*)(Kp + (size_t)(k0 + l) * D_ + c4);
            kv.x = tf32r(kv.x); kv.y = tf32r(kv.y); kv.z = tf32r(kv.z); kv.w = tf32r(kv.w);
            *(float4*)(Ks + p * KS_STR + c4) = kv;
            float4 vv = *(const float4*)(Vp + (size_t)(k0 + l) * D_ + c4);
            vv.x = tf32r(vv.x); vv.y = tf32r(vv.y); vv.z = tf32r(vv.z); vv.w = tf32r(vv.w);
            *(float4*)(Vs + p * VS_STR + c4) = vv;
        }
        if (tid < BN) Msl[tid] = Mp[k0 + tid] ? 0.f : -1.0e30f;  // logical order
        __syncthreads();

        // ---- fused per-n-tile pipeline over this warp's 64 phys k-cols ----
        #pragma unroll
        for (int nt = 0; nt < 8; ++nt) {
            // GEMM1: Sf = Q . K^T for 32 rows x 8 phys cols (B shared across mt)
            float Sf0[4] = {0.f, 0.f, 0.f, 0.f};
            float Sf1[4] = {0.f, 0.f, 0.f, 0.f};
            const float* kb = Ks + (64 * kh + 8 * nt + g) * KS_STR + j;
            #pragma unroll
            for (int s = 0; s < 8; ++s) {
                uint32_t b0 = __float_as_uint(kb[8 * s]);
                uint32_t b1 = __float_as_uint(kb[8 * s + 4]);
                mma8(Sf0, Qa[0][s], b0, b1);
                mma8(Sf1, Qa[1][s], b0, b1);
            }

            // softmax (max-free, log2 domain); P overwrites Sf
            float2 mm = *(const float2*)(Msl + 64 * kh + 16 * j + 2 * nt);
            {
                float2 b00 = *(const float2*)(bp0 + k0 + 2 * nt);
                float2 b01 = *(const float2*)(bp1 + k0 + 2 * nt);
                float p0 = tf32r(ex2f(fmaf(Sf0[0], C1, fmaf(b00.x, C2, mm.x))));
                float p1 = tf32r(ex2f(fmaf(Sf0[1], C1, fmaf(b00.y, C2, mm.y))));
                float p2 = tf32r(ex2f(fmaf(Sf0[2], C1, fmaf(b01.x, C2, mm.x))));
                float p3 = tf32r(ex2f(fmaf(Sf0[3], C1, fmaf(b01.y, C2, mm.y))));
                lacc[0] += p0 + p1; lacc[1] += p2 + p3;
                Sf0[0] = p0; Sf0[1] = p1; Sf0[2] = p2; Sf0[3] = p3;
            }
            {
                float2 b10 = *(const float2*)(bp2 + k0 + 2 * nt);
                float2 b11 = *(const float2*)(bp3 + k0 + 2 * nt);
                float p0 = tf32r(ex2f(fmaf(Sf1[0], C1, fmaf(b10.x, C2, mm.x))));
                float p1 = tf32r(ex2f(fmaf(Sf1[1], C1, fmaf(b10.y, C2, mm.y))));
                float p2 = tf32r(ex2f(fmaf(Sf1[2], C1, fmaf(b11.x, C2, mm.x))));
                float p3 = tf32r(ex2f(fmaf(Sf1[3], C1, fmaf(b11.y, C2, mm.y))));
                lacc[2] += p0 + p1; lacc[3] += p2 + p3;
                Sf1[0] = p0; Sf1[1] = p1; Sf1[2] = p2; Sf1[3] = p3;
            }

            // C-frag -> A-frag via quad shuffles (both m-tiles)
            uint32_t paA[4], paB[4];
            {
                float x0 = __shfl_sync(0xffffffffu, Sf0[0], srcA);
                float x1 = __shfl_sync(0xffffffffu, Sf0[1], srcA);
                float x2 = __shfl_sync(0xffffffffu, Sf0[2], srcA);
                float x3 = __shfl_sync(0xffffffffu, Sf0[3], srcA);
                float y0 = __shfl_sync(0xffffffffu, Sf0[0], srcB);
                float y1 = __shfl_sync(0xffffffffu, Sf0[1], srcB);
                float y2 = __shfl_sync(0xffffffffu, Sf0[2], srcB);
                float y3 = __shfl_sync(0xffffffffu, Sf0[3], srcB);
                paA[0] = __float_as_uint(hi ? x1 : x0);
                paA[1] = __float_as_uint(hi ? x3 : x2);
                paA[2] = __float_as_uint(hi ? y1 : y0);
                paA[3] = __float_as_uint(hi ? y3 : y2);
            }
            {
                float x0 = __shfl_sync(0xffffffffu, Sf1[0], srcA);
                float x1 = __shfl_sync(0xffffffffu, Sf1[1], srcA);
                float x2 = __shfl_sync(0xffffffffu, Sf1[2], srcA);
                float x3 = __shfl_sync(0xffffffffu, Sf1[3], srcA);
                float y0 = __shfl_sync(0xffffffffu, Sf1[0], srcB);
                float y1 = __shfl_sync(0xffffffffu, Sf1[1], srcB);
                float y2 = __shfl_sync(0xffffffffu, Sf1[2], srcB);
                float y3 = __shfl_sync(0xffffffffu, Sf1[3], srcB);
                paB[0] = __float_as_uint(hi ? x1 : x0);
                paB[1] = __float_as_uint(hi ? x3 : x2);
                paB[2] = __float_as_uint(hi ? y1 : y0);
                paB[3] = __float_as_uint(hi ? y3 : y2);
            }

            // GEMM2: O += P . V for this 8-col k-chunk (B shared across mt)
            const float* vb = Vs + (64 * kh + 8 * nt + j) * VS_STR + g;
            #pragma unroll
            for (int nd = 0; nd < 8; ++nd) {
                uint32_t b0 = __float_as_uint(vb[8 * nd]);
                uint32_t b1 = __float_as_uint(vb[8 * nd + 4 * VS_STR]);
                mma8(Oc[0][nd], paA, b0, b1);
                mma8(Oc[1][nd], paB, b0, b1);
            }
        }
    }

    // ---- epilogue: merge the two k-halves, normalize, store ----
    __syncthreads();
    #pragma unroll
    for (int e = 0; e < 4; ++e) {
        lacc[e] += __shfl_xor_sync(0xffffffffu, lacc[e], 1);
        lacc[e] += __shfl_xor_sync(0xffffffffu, lacc[e], 2);
    }
    float* Os = (float*)smem_raw;                 // [128][64] stride 66
    float* Ls = (float*)(smem_raw + OFF_LS);      // [128]

    if (kh == 1) {
        #pragma unroll
        for (int mt = 0; mt < 2; ++mt) {
            const int r0 = wq * 32 + 16 * mt + g;
            const int r1 = r0 + 8;
            #pragma unroll
            for (int nd = 0; nd < 8; ++nd) {
                *(float2*)(Os + r0 * OS_STR + 8 * nd + 2 * j) =
                    make_float2(Oc[mt][nd][0], Oc[mt][nd][1]);
                *(float2*)(Os + r1 * OS_STR + 8 * nd + 2 * j) =
                    make_float2(Oc[mt][nd][2], Oc[mt][nd][3]);
            }
            if (j == 0) { Ls[r0] = lacc[2 * mt]; Ls[r1] = lacc[2 * mt + 1]; }
        }
    }
    __syncthreads();
    if (kh == 0) {
        #pragma unroll
        for (int mt = 0; mt < 2; ++mt) {
            const int r0 = wq * 32 + 16 * mt + g;
            const int r1 = r0 + 8;
            const float i0 = 1.0f / (lacc[2 * mt]     + Ls[r0]);
            const float i1 = 1.0f / (lacc[2 * mt + 1] + Ls[r1]);
            float* o0 = OUT + bh * (size_t)(L_ * D_) + (size_t)(q0 + r0) * D_ + 2 * j;
            float* o1 = OUT + bh * (size_t)(L_ * D_) + (size_t)(q0 + r1) * D_ + 2 * j;
            #pragma unroll
            for (int nd = 0; nd < 8; ++nd) {
                float2 a = *(const float2*)(Os + r0 * OS_STR + 8 * nd + 2 * j);
                float2 c = *(const float2*)(Os + r1 * OS_STR + 8 * nd + 2 * j);
                *(float2*)(o0 + 8 * nd) =
                    make_float2((Oc[mt][nd][0] + a.x) * i0, (Oc[mt][nd][1] + a.y) * i0);
                *(float2*)(o1 + 8 * nd) =
                    make_float2((Oc[mt][nd][2] + c.x) * i1, (Oc[mt][nd][3] + c.y) * i1);
            }
        }
    }
}

extern "C" void kernel_launch(void* const* d_in, const int* in_sizes, int n_in,
                              void* d_out, int out_size)
{
    const float* Q    = (const float*)d_in[0];
    const float* K    = (const float*)d_in[1];
    const float* V    = (const float*)d_in[2];
    const int*   AM   = (const int*)d_in[3];
    const float* BIAS = (const float*)d_in[4];
    float*       OUT  = (float*)d_out;

    cudaFuncSetAttribute(SelfAttention_53369263620701_kernel,
                         cudaFuncAttributeMaxDynamicSharedMemorySize, SMEM_BYTES);

    dim3 grid(H_, NQT, B_);   // h fastest: co-scheduled heads share bias rows in L2
    dim3 block(256);
    SelfAttention_53369263620701_kernel<<<grid, block, SMEM_BYTES>>>(
        Q, K, V, AM, BIAS, OUT);
}